// round 11
// baseline (speedup 1.0000x reference)
#include <cuda_runtime.h>

// DIN attention layer, B=2048, L=200, E=128, H=64, fp32.
// attn_in@W1 = qa_b + k @ M_b (per-batch M).
// E-PAIR vectorization: fma.rn.f32x2 contracts (e,e+1) per instruction.
//   kTp[ep][l]   = (k[2ep][l], k[2ep+1][l])          (ull, broadcast loads)
//   Mp[ep][2h+s] = m[2ep+s][h]                       (lane LDS.128 -> 2 pairs)
//   h1T[hp][j]   = (h1[j][2hp], h1[j][2hp+1])        (ull, broadcast loads)
//   W2p[hp][2h'+s] = W2[2hp+s][h']                   (lane LDS.128 -> 2 pairs)
// Zero dup movs in both GEMM inner loops. 20 warps, one 10-key tile each.

namespace {
constexpr int Bn = 2048;
constexpr int L  = 200;
constexpr int E  = 128;
constexpr int H  = 64;
constexpr int NT = 640;
constexpr int NW = 20;
constexpr int TK = 10;
constexpr int KPS = 206;   // kTp row stride in ull (200 used + pad; 16B-aligned rows)
constexpr int H1S = 10;    // h1T row stride in ull (80B, 16B-aligned)

// float offsets
constexpr int OFF_KTP = 0;              // 64*206 ull = 26368 f
constexpr int OFF_MP  = 26368;          // 8192 f
constexpr int OFF_W2P = 34560;          // 4096 f
constexpr int OFF_H1  = 38656;          // 20*32*10 ull = 12800 f
constexpr int OFF_Q   = 51456;          // 128
constexpr int OFF_QA  = 51584;          // 64
constexpr int OFF_W3  = 51648;          // 64
constexpr int OFF_B2  = 51712;          // 64
constexpr int OFF_S   = 51776;          // 208
constexpr int OFF_MK  = 51984;          // 208
constexpr int OFF_RED = 52192;          // 64
constexpr int OFF_PART= 52256;          // 1280
constexpr int SMEM_FLOATS = 53536;      // 214144 bytes
}

typedef unsigned long long ull;

__device__ __forceinline__ void ffma2(ull& d, ull a, ull b) {
    asm("fma.rn.f32x2 %0, %1, %2, %0;" : "+l"(d) : "l"(a), "l"(b));
}
__device__ __forceinline__ ull pack2(float x, float y) {
    ull r;
    asm("mov.b64 %0, {%1, %2};" : "=l"(r) : "f"(x), "f"(y));
    return r;
}
__device__ __forceinline__ float2 upk(ull v) {
    float2 r;
    asm("mov.b64 {%0, %1}, %2;" : "=f"(r.x), "=f"(r.y) : "l"(v));
    return r;
}

__global__ __launch_bounds__(NT, 1)
void din_kernel(const float* __restrict__ query,
                const float* __restrict__ keys,
                const int*   __restrict__ mask,
                const float* __restrict__ W1,
                const float* __restrict__ b1,
                const float* __restrict__ W2,
                const float* __restrict__ b2,
                const float* __restrict__ W3,
                const float* __restrict__ b3,
                const float* __restrict__ nohist,
                float* __restrict__ out)
{
    extern __shared__ __align__(16) float sm[];
    ull*   sKTP = reinterpret_cast<ull*>(sm + OFF_KTP);
    float* sMp  = sm + OFF_MP;
    float* sW2p = sm + OFF_W2P;
    float* sH1  = sm + OFF_H1;
    float* sQ   = sm + OFF_Q;
    float* sQa  = sm + OFF_QA;
    float* sW3  = sm + OFF_W3;
    float* sB2  = sm + OFF_B2;
    float* sS   = sm + OFF_S;
    int*   sMk  = reinterpret_cast<int*>(sm + OFF_MK);
    float* sRed = sm + OFF_RED;
    float* sPart= sm + OFF_PART;

    const int tid  = threadIdx.x;
    const int lane = tid & 31;
    const int warp = tid >> 5;
    const int b    = blockIdx.x;

    // ---------- stage: keys -> e-pair transposed kTp[ep][l] ----------
    {
        const float4* kb4 = reinterpret_cast<const float4*>(keys + (size_t)b * (L * E));
        #pragma unroll
        for (int it = 0; it < 10; ++it) {
            const int j  = it * NT + tid;        // 0..6399
            const int e4 = j / 200;              // 0..31 (pair-group: e = 4e4..4e4+3)
            const int lp = j - e4 * 200;         // 0..199
            const float4 v = kb4[lp * 32 + e4];
            *reinterpret_cast<float2*>(sKTP + (2 * e4)     * KPS + lp) = make_float2(v.x, v.y);
            *reinterpret_cast<float2*>(sKTP + (2 * e4 + 1) * KPS + lp) = make_float2(v.z, v.w);
        }
    }
    // W2p[hp][2h'+s] = W2[2hp+s][h']
    for (int i = tid; i < H * H; i += NT) {
        const int hp = i >> 7, c = i & 127;
        const int hq = c >> 1, s = c & 1;
        sW2p[hp * 128 + c] = W2[(2 * hp + s) * H + hq];
    }
    if (tid < E) sQ[tid] = query[b * E + tid];
    if (tid < H) { sW3[tid] = W3[tid]; sB2[tid] = b2[tid]; }
    if (tid < L) sMk[tid] = mask[b * L + tid];
    __syncthreads();

    // ---------- per-batch M (e-pair interleaved) + qa ----------
    for (int i = tid; i < E * H; i += NT) {
        const int e = i >> 6, h = i & (H - 1);
        const float v = W1[(128 + e) * H + h] - W1[(384 + e) * H + h]
                      + sQ[e] * W1[(256 + e) * H + h];
        sMp[(e >> 1) * 128 + 2 * h + (e & 1)] = v;
    }
    {   // qa partials: 10 e-chunks x 64 h
        const int h = tid & (H - 1);
        const int r = tid >> 6;
        const int e0 = r * 13;
        const int e1 = (e0 + 13 < E) ? e0 + 13 : E;
        float acc = 0.f;
        for (int e = e0; e < e1; ++e)
            acc += sQ[e] * (W1[e * H + h] + W1[(384 + e) * H + h]);
        sPart[r * H + h] = acc;
    }
    __syncthreads();
    if (tid < H) {
        float acc = b1[tid];
        #pragma unroll
        for (int r = 0; r < 10; ++r) acc += sPart[r * H + tid];
        sQa[tid] = acc;
    }
    __syncthreads();

    // ---------- GEMM1: warp = one 10-key tile; 64 e-pair steps ----------
    const int l0 = warp * TK;
    {
        const ull*   ktw = sKTP + warp * TK;
        const float* mpl = sMp + 4 * lane;

        ull acc[10][2];       // [j][h-local]; each ull = (e-even, e-odd) partials
        #pragma unroll
        for (int j = 0; j < 10; ++j) { acc[j][0] = 0ull; acc[j][1] = 0ull; }

        #pragma unroll 2
        for (int ep = 0; ep < 64; ++ep) {
            const ull* kr = ktw + ep * KPS;
            const ulonglong2 kA = *reinterpret_cast<const ulonglong2*>(kr);
            const ulonglong2 kB = *reinterpret_cast<const ulonglong2*>(kr + 2);
            const ulonglong2 kC = *reinterpret_cast<const ulonglong2*>(kr + 4);
            const ulonglong2 kD = *reinterpret_cast<const ulonglong2*>(kr + 6);
            const ulonglong2 kE = *reinterpret_cast<const ulonglong2*>(kr + 8);
            const float4 mv = *reinterpret_cast<const float4*>(mpl + ep * 128);
            const ull m0 = pack2(mv.x, mv.y);   // h = 2*lane
            const ull m1 = pack2(mv.z, mv.w);   // h = 2*lane+1
            ffma2(acc[0][0], kA.x, m0); ffma2(acc[0][1], kA.x, m1);
            ffma2(acc[1][0], kA.y, m0); ffma2(acc[1][1], kA.y, m1);
            ffma2(acc[2][0], kB.x, m0); ffma2(acc[2][1], kB.x, m1);
            ffma2(acc[3][0], kB.y, m0); ffma2(acc[3][1], kB.y, m1);
            ffma2(acc[4][0], kC.x, m0); ffma2(acc[4][1], kC.x, m1);
            ffma2(acc[5][0], kC.y, m0); ffma2(acc[5][1], kC.y, m1);
            ffma2(acc[6][0], kD.x, m0); ffma2(acc[6][1], kD.x, m1);
            ffma2(acc[7][0], kD.y, m0); ffma2(acc[7][1], kD.y, m1);
            ffma2(acc[8][0], kE.x, m0); ffma2(acc[8][1], kE.x, m1);
            ffma2(acc[9][0], kE.y, m0); ffma2(acc[9][1], kE.y, m1);
        }

        // h1T[lane][j] = (relu(.+qa[2l]), relu(.+qa[2l+1])) as ull pairs
        float* h1w = sH1 + warp * (32 * H1S * 2);
        const float qax = sQa[2 * lane], qay = sQa[2 * lane + 1];
        #pragma unroll
        for (int jp = 0; jp < 5; ++jp) {
            const float2 a0 = upk(acc[2 * jp][0]);
            const float2 a1 = upk(acc[2 * jp][1]);
            const float2 b0 = upk(acc[2 * jp + 1][0]);
            const float2 b1v= upk(acc[2 * jp + 1][1]);
            float4 o;
            o.x = fmaxf(a0.x + a0.y + qax, 0.f);
            o.y = fmaxf(a1.x + a1.y + qay, 0.f);
            o.z = fmaxf(b0.x + b0.y + qax, 0.f);
            o.w = fmaxf(b1v.x + b1v.y + qay, 0.f);
            *reinterpret_cast<float4*>(h1w + (lane * H1S + 2 * jp) * 2) = o;
        }
    }
    __syncwarp();

    // ---------- GEMM2: 32 h-pair steps ----------
    {
        const ull*   h1u = reinterpret_cast<const ull*>(sH1 + warp * (32 * H1S * 2));
        const float* w2l = sW2p + 4 * lane;

        ull acc2[10][2];
        #pragma unroll
        for (int j = 0; j < 10; ++j) { acc2[j][0] = 0ull; acc2[j][1] = 0ull; }

        #pragma unroll 2
        for (int hp = 0; hp < 32; ++hp) {
            const ull* hr = h1u + hp * H1S;
            const ulonglong2 hA = *reinterpret_cast<const ulonglong2*>(hr);
            const ulonglong2 hB = *reinterpret_cast<const ulonglong2*>(hr + 2);
            const ulonglong2 hC = *reinterpret_cast<const ulonglong2*>(hr + 4);
            const ulonglong2 hD = *reinterpret_cast<const ulonglong2*>(hr + 6);
            const ulonglong2 hE = *reinterpret_cast<const ulonglong2*>(hr + 8);
            const float4 wv = *reinterpret_cast<const float4*>(w2l + hp * 128);
            const ull w0 = pack2(wv.x, wv.y);   // h' = 2*lane
            const ull w1 = pack2(wv.z, wv.w);   // h' = 2*lane+1
            ffma2(acc2[0][0], hA.x, w0); ffma2(acc2[0][1], hA.x, w1);
            ffma2(acc2[1][0], hA.y, w0); ffma2(acc2[1][1], hA.y, w1);
            ffma2(acc2[2][0], hB.x, w0); ffma2(acc2[2][1], hB.x, w1);
            ffma2(acc2[3][0], hB.y, w0); ffma2(acc2[3][1], hB.y, w1);
            ffma2(acc2[4][0], hC.x, w0); ffma2(acc2[4][1], hC.x, w1);
            ffma2(acc2[5][0], hC.y, w0); ffma2(acc2[5][1], hC.y, w1);
            ffma2(acc2[6][0], hD.x, w0); ffma2(acc2[6][1], hD.x, w1);
            ffma2(acc2[7][0], hD.y, w0); ffma2(acc2[7][1], hD.y, w1);
            ffma2(acc2[8][0], hE.x, w0); ffma2(acc2[8][1], hE.x, w1);
            ffma2(acc2[9][0], hE.y, w0); ffma2(acc2[9][1], hE.y, w1);
        }

        // layer 3: s[j] = relu(h2[j]+b2) . W3 + b3  (butterfly over lanes)
        const float w3x = sW3[2 * lane], w3y = sW3[2 * lane + 1];
        const float b2x = sB2[2 * lane], b2y = sB2[2 * lane + 1];
        const float b3v = b3[0];
        #pragma unroll
        for (int jp = 0; jp < 5; ++jp) {
            const float2 e0 = upk(acc2[2 * jp][0]);
            const float2 e1 = upk(acc2[2 * jp][1]);
            const float2 f0 = upk(acc2[2 * jp + 1][0]);
            const float2 f1 = upk(acc2[2 * jp + 1][1]);
            float pa = fmaxf(e0.x + e0.y + b2x, 0.f) * w3x
                     + fmaxf(e1.x + e1.y + b2y, 0.f) * w3y;
            float pb = fmaxf(f0.x + f0.y + b2x, 0.f) * w3x
                     + fmaxf(f1.x + f1.y + b2y, 0.f) * w3y;
            #pragma unroll
            for (int o = 16; o > 0; o >>= 1) {
                pa += __shfl_xor_sync(0xffffffffu, pa, o);
                pb += __shfl_xor_sync(0xffffffffu, pb, o);
            }
            if (lane == 0) {
                sS[l0 + 2 * jp]     = pa + b3v;
                sS[l0 + 2 * jp + 1] = pb + b3v;
            }
        }
    }
    __syncthreads();

    // ---------- masked softmax over L ----------
    float vmax = -3.0e38f;
    if (tid < L && sMk[tid]) vmax = sS[tid];
    #pragma unroll
    for (int o = 16; o > 0; o >>= 1)
        vmax = fmaxf(vmax, __shfl_xor_sync(0xffffffffu, vmax, o));
    if (lane == 0) sRed[warp] = vmax;
    __syncthreads();
    if (warp == 0) {
        float v = (lane < NW) ? sRed[lane] : -3.0e38f;
        #pragma unroll
        for (int o = 16; o > 0; o >>= 1)
            v = fmaxf(v, __shfl_xor_sync(0xffffffffu, v, o));
        if (lane == 0) sRed[0] = v;
    }
    __syncthreads();
    const float smax = sRed[0];

    float p = 0.f, mc = 0.f;
    if (tid < L) {
        const int m = sMk[tid];
        p  = m ? __expf(sS[tid] - smax) : 0.f;
        mc = m ? 1.f : 0.f;
    }
    float sp = p, sc = mc;
    #pragma unroll
    for (int o = 16; o > 0; o >>= 1) {
        sp += __shfl_xor_sync(0xffffffffu, sp, o);
        sc += __shfl_xor_sync(0xffffffffu, sc, o);
    }
    if (lane == 0) { sRed[warp] = sp; sRed[NW + warp] = sc; }
    __syncthreads();
    if (tid < L) sS[tid] = p;
    if (warp == 0) {
        float a = (lane < NW) ? sRed[lane] : 0.f;
        float c = (lane < NW) ? sRed[NW + lane] : 0.f;
        #pragma unroll
        for (int o = 16; o > 0; o >>= 1) {
            a += __shfl_xor_sync(0xffffffffu, a, o);
            c += __shfl_xor_sync(0xffffffffu, c, o);
        }
        if (lane == 0) { sRed[0] = a; sRed[1] = c; }
    }
    __syncthreads();
    const float denom  = sRed[0];
    const bool  allpad = (sRed[1] < 0.5f);
    const float inv    = allpad ? 0.f : (1.0f / denom);

    // ---------- weighted sum of keys (from kTp pairs) ----------
    {
        const int ep = tid & 63;         // e-pair
        const int r  = tid >> 6;         // 0..9, 20 keys each
        float ax = 0.f, ay = 0.f;
        const ull* kb = sKTP + ep * KPS;
        #pragma unroll
        for (int l2 = 0; l2 < 10; ++l2) {
            const int l = r * 20 + 2 * l2;
            const float4 kv = *reinterpret_cast<const float4*>(kb + l);
            const float2 pv = *reinterpret_cast<const float2*>(sS + l);
            ax += pv.x * kv.x + pv.y * kv.z;   // e = 2*ep
            ay += pv.x * kv.y + pv.y * kv.w;   // e = 2*ep+1
        }
        sPart[r * E + 2 * ep]     = ax;
        sPart[r * E + 2 * ep + 1] = ay;
    }
    __syncthreads();
    if (tid < E) {
        float o = 0.f;
        #pragma unroll
        for (int r = 0; r < 10; ++r) o += sPart[r * E + tid];
        o *= inv;
        if (allpad) o = nohist[tid];
        out[b * E + tid] = o;
    }
}

extern "C" void kernel_launch(void* const* d_in, const int* in_sizes, int n_in,
                              void* d_out, int out_size) {
    const float* query = (const float*)d_in[0];
    const float* keys  = (const float*)d_in[1];
    const int*   mask  = (const int*)  d_in[2];
    const float* W1    = (const float*)d_in[3];
    const float* b1    = (const float*)d_in[4];
    const float* W2    = (const float*)d_in[5];
    const float* b2    = (const float*)d_in[6];
    const float* W3    = (const float*)d_in[7];
    const float* b3    = (const float*)d_in[8];
    const float* nh    = (const float*)d_in[9];
    float* out = (float*)d_out;

    cudaFuncSetAttribute(din_kernel, cudaFuncAttributeMaxDynamicSharedMemorySize,
                         SMEM_FLOATS * (int)sizeof(float));
    din_kernel<<<Bn, NT, SMEM_FLOATS * sizeof(float)>>>(
        query, keys, mask, W1, b1, W2, b2, W3, b3, nh, out);
}

// round 14
// speedup vs baseline: 1.0359x; 1.0359x over previous
#include <cuda_runtime.h>
#include <cstdint>

// DIN attention, B=2048, L=200, E=128, H=64, fp32.
// attn_in@W1 = qa_b + k @ M_b (per-batch M).
// 2 CTAs/SM (320 thr, ~104KB smem each): independent CTAs interleave phases.
// Keys are NOT staged: GEMM1 reads warp-tile keys from gmem (broadcast LDG.128,
// L1-line reuse), weighted sum re-reads keys coalesced. f32x2 e-pair math,
// Mp/W2p interleaved so smem LDS.128 IS the f32x2 operand (zero packing movs).

namespace {
constexpr int Bn = 2048;
constexpr int L  = 200;
constexpr int E  = 128;
constexpr int H  = 64;
constexpr int NT = 320;   // 10 warps
constexpr int NW = 10;

// float offsets in dynamic smem
constexpr int OFF_MP  = 0;       // 64 ep x 128 = 8192 f (32KB)
constexpr int OFF_W2P = 8192;    // 32 hp x 128 = 4096 f (16KB)
constexpr int OFF_H1  = 12288;   // 10 warps x 32 hp x 40 f = 12800 f (51.2KB)
constexpr int OFF_QA  = 25088;   // 64
constexpr int OFF_W3  = 25152;   // 64
constexpr int OFF_B2  = 25216;   // 64
constexpr int OFF_S   = 25280;   // 208
constexpr int OFF_MK  = 25488;   // 208
constexpr int OFF_RED = 25696;   // 32
constexpr int OFF_PART= 25728;   // 320
constexpr int SMEM_FLOATS = 26048;   // 104192 bytes
}

typedef unsigned long long ull;

__device__ __forceinline__ void ffma2(ull& d, ull a, ull b) {
    asm("fma.rn.f32x2 %0, %1, %2, %0;" : "+l"(d) : "l"(a), "l"(b));
}
__device__ __forceinline__ ull pack2(float x, float y) {
    ull r;
    asm("mov.b64 %0, {%1, %2};" : "=l"(r) : "f"(x), "f"(y));
    return r;
}
__device__ __forceinline__ float2 upk(ull v) {
    float2 r;
    asm("mov.b64 {%0, %1}, %2;" : "=f"(r.x), "=f"(r.y) : "l"(v));
    return r;
}
__device__ __forceinline__ ulonglong2 ldg128(const void* p) {
    ulonglong2 r;
    asm("ld.global.nc.v2.u64 {%0, %1}, [%2];" : "=l"(r.x), "=l"(r.y) : "l"(p));
    return r;
}

__global__ __launch_bounds__(NT, 2)
void din_kernel(const float* __restrict__ query,
                const float* __restrict__ keys,
                const int*   __restrict__ mask,
                const float* __restrict__ W1,
                const float* __restrict__ b1,
                const float* __restrict__ W2,
                const float* __restrict__ b2,
                const float* __restrict__ W3,
                const float* __restrict__ b3,
                const float* __restrict__ nohist,
                float* __restrict__ out)
{
    extern __shared__ __align__(16) float sm[];
    float* sMp  = sm + OFF_MP;
    float* sW2p = sm + OFF_W2P;
    float* sH1  = sm + OFF_H1;
    float* sQa  = sm + OFF_QA;
    float* sW3  = sm + OFF_W3;
    float* sB2  = sm + OFF_B2;
    float* sS   = sm + OFF_S;
    int*   sMk  = reinterpret_cast<int*>(sm + OFF_MK);
    float* sRed = sm + OFF_RED;
    float* sPart= sm + OFF_PART;

    const int tid  = threadIdx.x;
    const int lane = tid & 31;
    const int warp = tid >> 5;
    const int b    = blockIdx.x;

    const float* qg = query + (size_t)b * E;

    // ---------- phase A (no barrier): build Mp, W2p, qa partials, load small ----------
    // Mp[ep][2h+s] = m[2ep+s][h] where m[e][h] = W1b - W1d + q[e]*W1c
    for (int i = tid; i < E * H; i += NT) {
        const int e = i >> 6, h = i & (H - 1);
        const float v = __ldg(W1 + (128 + e) * H + h) - __ldg(W1 + (384 + e) * H + h)
                      + __ldg(qg + e) * __ldg(W1 + (256 + e) * H + h);
        sMp[(e >> 1) * 128 + 2 * h + (e & 1)] = v;
    }
    // W2p[hp][2h'+s] = W2[2hp+s][h']
    for (int i = tid; i < H * H; i += NT) {
        const int hp = i >> 7, c = i & 127;
        sW2p[i] = __ldg(W2 + (2 * hp + (c & 1)) * H + (c >> 1));
    }
    {   // qa partials: 5 e-chunks x 64 h
        const int h = tid & (H - 1);
        const int r = tid >> 6;              // 0..4
        const int e0 = r * 26;
        const int e1 = (e0 + 26 < E) ? e0 + 26 : E;
        float acc = 0.f;
        for (int e = e0; e < e1; ++e)
            acc += __ldg(qg + e) * (__ldg(W1 + e * H + h) + __ldg(W1 + (384 + e) * H + h));
        sPart[r * H + h] = acc;
    }
    if (tid < H) { sW3[tid] = W3[tid]; sB2[tid] = b2[tid]; }
    if (tid < L) sMk[tid] = mask[b * L + tid];
    __syncthreads();

    if (tid < H) {
        float acc = b1[tid];
        #pragma unroll
        for (int r = 0; r < 5; ++r) acc += sPart[r * H + tid];
        sQa[tid] = acc;
    }
    __syncthreads();

    // ---------- scorer: warp owns keys [warp*20, warp*20+20), 2 passes of 10 ----------
    const float* kwarp = keys + (size_t)b * (L * E) + warp * 20 * E;
    const ulonglong2* mrow  = reinterpret_cast<const ulonglong2*>(sMp  + 4 * lane);
    const ulonglong2* w2row = reinterpret_cast<const ulonglong2*>(sW2p + 4 * lane);
    float* h1w = sH1 + warp * 1280;          // 32 rows x 40 f
    const float qax = sQa[2 * lane], qay = sQa[2 * lane + 1];
    const float w3x = sW3[2 * lane], w3y = sW3[2 * lane + 1];
    const float b2x = sB2[2 * lane], b2y = sB2[2 * lane + 1];
    const float b3v = b3[0];

    #pragma unroll
    for (int pass = 0; pass < 2; ++pass) {
        const char* kp = reinterpret_cast<const char*>(kwarp + pass * 10 * E);

        // GEMM1: 10 keys x 64 h, K=128 (32 steps of 4 e)
        ull acc[10][2];
        #pragma unroll
        for (int j = 0; j < 10; ++j) { acc[j][0] = 0ull; acc[j][1] = 0ull; }

        for (int ep2 = 0; ep2 < 32; ++ep2) {
            ulonglong2 kv[10];
            #pragma unroll
            for (int j = 0; j < 10; ++j)
                kv[j] = ldg128(kp + j * (E * 4) + ep2 * 16);
            const ulonglong2 mA = mrow[(2 * ep2) * 32];
            const ulonglong2 mB = mrow[(2 * ep2 + 1) * 32];
            #pragma unroll
            for (int j = 0; j < 10; ++j) {
                ffma2(acc[j][0], kv[j].x, mA.x); ffma2(acc[j][1], kv[j].x, mA.y);
                ffma2(acc[j][0], kv[j].y, mB.x); ffma2(acc[j][1], kv[j].y, mB.y);
            }
        }

        // h1 write: lane owns hp=lane row; ull j = (h1[j][2l], h1[j][2l+1])
        {
            float* dst = h1w + lane * 40 + pass * 20;
            #pragma unroll
            for (int jp = 0; jp < 5; ++jp) {
                const float2 a0 = upk(acc[2 * jp][0]);
                const float2 a1 = upk(acc[2 * jp][1]);
                const float2 c0 = upk(acc[2 * jp + 1][0]);
                const float2 c1 = upk(acc[2 * jp + 1][1]);
                float4 o;
                o.x = fmaxf(a0.x + a0.y + qax, 0.f);
                o.y = fmaxf(a1.x + a1.y + qay, 0.f);
                o.z = fmaxf(c0.x + c0.y + qax, 0.f);
                o.w = fmaxf(c1.x + c1.y + qay, 0.f);
                *reinterpret_cast<float4*>(dst + 4 * jp) = o;
            }
        }
        __syncwarp();

        // GEMM2: 10 keys x 64 h', K=64 (32 h-pair steps)
        ull acc2[10][2];
        #pragma unroll
        for (int j = 0; j < 10; ++j) { acc2[j][0] = 0ull; acc2[j][1] = 0ull; }

        for (int hp = 0; hp < 32; ++hp) {
            const ull* hrow = reinterpret_cast<const ull*>(h1w + hp * 40 + pass * 20);
            const ulonglong2 hA = *reinterpret_cast<const ulonglong2*>(hrow);
            const ulonglong2 hB = *reinterpret_cast<const ulonglong2*>(hrow + 2);
            const ulonglong2 hC = *reinterpret_cast<const ulonglong2*>(hrow + 4);
            const ulonglong2 hD = *reinterpret_cast<const ulonglong2*>(hrow + 6);
            const ulonglong2 hE = *reinterpret_cast<const ulonglong2*>(hrow + 8);
            const ulonglong2 wv = w2row[hp * 32];
            ffma2(acc2[0][0], hA.x, wv.x); ffma2(acc2[0][1], hA.x, wv.y);
            ffma2(acc2[1][0], hA.y, wv.x); ffma2(acc2[1][1], hA.y, wv.y);
            ffma2(acc2[2][0], hB.x, wv.x); ffma2(acc2[2][1], hB.x, wv.y);
            ffma2(acc2[3][0], hB.y, wv.x); ffma2(acc2[3][1], hB.y, wv.y);
            ffma2(acc2[4][0], hC.x, wv.x); ffma2(acc2[4][1], hC.x, wv.y);
            ffma2(acc2[5][0], hC.y, wv.x); ffma2(acc2[5][1], hC.y, wv.y);
            ffma2(acc2[6][0], hD.x, wv.x); ffma2(acc2[6][1], hD.x, wv.y);
            ffma2(acc2[7][0], hD.y, wv.x); ffma2(acc2[7][1], hD.y, wv.y);
            ffma2(acc2[8][0], hE.x, wv.x); ffma2(acc2[8][1], hE.x, wv.y);
            ffma2(acc2[9][0], hE.y, wv.x); ffma2(acc2[9][1], hE.y, wv.y);
        }

        // layer 3 + butterfly
        const int l0 = warp * 20 + pass * 10;
        #pragma unroll
        for (int jp = 0; jp < 5; ++jp) {
            const float2 e0 = upk(acc2[2 * jp][0]);
            const float2 e1 = upk(acc2[2 * jp][1]);
            const float2 f0 = upk(acc2[2 * jp + 1][0]);
            const float2 f1 = upk(acc2[2 * jp + 1][1]);
            float pa = fmaxf(e0.x + e0.y + b2x, 0.f) * w3x
                     + fmaxf(e1.x + e1.y + b2y, 0.f) * w3y;
            float pb = fmaxf(f0.x + f0.y + b2x, 0.f) * w3x
                     + fmaxf(f1.x + f1.y + b2y, 0.f) * w3y;
            #pragma unroll
            for (int o = 16; o > 0; o >>= 1) {
                pa += __shfl_xor_sync(0xffffffffu, pa, o);
                pb += __shfl_xor_sync(0xffffffffu, pb, o);
            }
            if (lane == 0) {
                sS[l0 + 2 * jp]     = pa + b3v;
                sS[l0 + 2 * jp + 1] = pb + b3v;
            }
        }
    }
    __syncthreads();

    // ---------- masked softmax over L ----------
    float vmax = -3.0e38f;
    if (tid < L && sMk[tid]) vmax = sS[tid];
    #pragma unroll
    for (int o = 16; o > 0; o >>= 1)
        vmax = fmaxf(vmax, __shfl_xor_sync(0xffffffffu, vmax, o));
    if (lane == 0) sRed[warp] = vmax;
    __syncthreads();
    if (warp == 0) {
        float v = (lane < NW) ? sRed[lane] : -3.0e38f;
        #pragma unroll
        for (int o = 16; o > 0; o >>= 1)
            v = fmaxf(v, __shfl_xor_sync(0xffffffffu, v, o));
        if (lane == 0) sRed[0] = v;
    }
    __syncthreads();
    const float smax = sRed[0];

    float p = 0.f, mc = 0.f;
    if (tid < L) {
        const int m = sMk[tid];
        p  = m ? __expf(sS[tid] - smax) : 0.f;
        mc = m ? 1.f : 0.f;
    }
    float sp = p, sc = mc;
    #pragma unroll
    for (int o = 16; o > 0; o >>= 1) {
        sp += __shfl_xor_sync(0xffffffffu, sp, o);
        sc += __shfl_xor_sync(0xffffffffu, sc, o);
    }
    if (lane == 0) { sRed[warp] = sp; sRed[NW + warp] = sc; }
    __syncthreads();
    if (tid < L) sS[tid] = p;
    if (warp == 0) {
        float a = (lane < NW) ? sRed[lane] : 0.f;
        float c = (lane < NW) ? sRed[NW + lane] : 0.f;
        #pragma unroll
        for (int o = 16; o > 0; o >>= 1) {
            a += __shfl_xor_sync(0xffffffffu, a, o);
            c += __shfl_xor_sync(0xffffffffu, c, o);
        }
        if (lane == 0) { sRed[0] = a; sRed[1] = c; }
    }
    __syncthreads();
    const float denom  = sRed[0];
    const bool  allpad = (sRed[1] < 0.5f);
    const float inv    = allpad ? 0.f : (1.0f / denom);

    // ---------- weighted sum of keys (coalesced gmem re-read) ----------
    if (tid < 256) {
        const int e = tid & 127;
        const int r = tid >> 7;              // 0..1, 100 keys each
        const float* kg = keys + (size_t)b * (L * E) + e;
        float acc = 0.f;
        const int lb = r * 100;
        #pragma unroll 4
        for (int l = lb; l < lb + 100; ++l)
            acc += sS[l] * __ldg(kg + l * E);
        sPart[r * E + e] = acc;
    }
    __syncthreads();
    if (tid < E) {
        float o = (sPart[tid] + sPart[E + tid]) * inv;
        if (allpad) o = nohist[tid];
        out[b * E + tid] = o;
    }
}

extern "C" void kernel_launch(void* const* d_in, const int* in_sizes, int n_in,
                              void* d_out, int out_size) {
    const float* query = (const float*)d_in[0];
    const float* keys  = (const float*)d_in[1];
    const int*   mask  = (const int*)  d_in[2];
    const float* W1    = (const float*)d_in[3];
    const float* b1    = (const float*)d_in[4];
    const float* W2    = (const float*)d_in[5];
    const float* b2    = (const float*)d_in[6];
    const float* W3    = (const float*)d_in[7];
    const float* b3    = (const float*)d_in[8];
    const float* nh    = (const float*)d_in[9];
    float* out = (float*)d_out;

    cudaFuncSetAttribute(din_kernel, cudaFuncAttributeMaxDynamicSharedMemorySize,
                         SMEM_FLOATS * (int)sizeof(float));
    din_kernel<<<Bn, NT, SMEM_FLOATS * sizeof(float)>>>(
        query, keys, mask, W1, b1, W2, b2, W3, b3, nh, out);
}

// round 15
// speedup vs baseline: 1.2689x; 1.2249x over previous
#include <cuda_runtime.h>
#include <cstdint>

// DIN attention, B=2048, L=200, E=128, H=64, fp32.
// attn_in@W1 = qa_b + k @ M_b (per-batch M).
// KEY INSIGHT: ~50% of keys are masked out; their scores underflow to exactly
// zero in the reference softmax. Compact unmasked indices first and run the
// MLP scorer + softmax + weighted sum ONLY on survivors (expected work halves).
// 2 CTAs/SM (320 thr, ~77KB smem): co-resident CTA absorbs tile imbalance.
// Keys read from gmem (broadcast LDG.128 rows, gathered via sIdx).

namespace {
constexpr int Bn = 2048;
constexpr int L  = 200;
constexpr int E  = 128;
constexpr int H  = 64;
constexpr int NT = 320;   // 10 warps
constexpr int NW = 10;

// float offsets in dynamic smem
constexpr int OFF_MP  = 0;       // 64 ep x 128 = 8192 f
constexpr int OFF_W2P = 8192;    // 32 hp x 128 = 4096 f
constexpr int OFF_H1  = 12288;   // 10 warps x 32 rows x 20 f = 6400 f
constexpr int OFF_QA  = 18688;   // 64
constexpr int OFF_W3  = 18752;   // 64
constexpr int OFF_B2  = 18816;   // 64
constexpr int OFF_S   = 18880;   // 208 (compacted scores/probs)
constexpr int OFF_IDX = 19088;   // 200 ints (compacted key indices)
constexpr int OFF_CNT = 19288;   // 8 ints (warp counts -> offsets, [7]=cnt)
constexpr int OFF_RED = 19296;   // 32
constexpr int OFF_PART= 19328;   // 320
constexpr int SMEM_FLOATS = 19648;   // 78592 bytes
}

typedef unsigned long long ull;

__device__ __forceinline__ void ffma2(ull& d, ull a, ull b) {
    asm("fma.rn.f32x2 %0, %1, %2, %0;" : "+l"(d) : "l"(a), "l"(b));
}
__device__ __forceinline__ float2 upk(ull v) {
    float2 r;
    asm("mov.b64 {%0, %1}, %2;" : "=f"(r.x), "=f"(r.y) : "l"(v));
    return r;
}
__device__ __forceinline__ ulonglong2 ldg128(const void* p) {
    ulonglong2 r;
    asm("ld.global.nc.v2.u64 {%0, %1}, [%2];" : "=l"(r.x), "=l"(r.y) : "l"(p));
    return r;
}

__global__ __launch_bounds__(NT, 2)
void din_kernel(const float* __restrict__ query,
                const float* __restrict__ keys,
                const int*   __restrict__ mask,
                const float* __restrict__ W1,
                const float* __restrict__ b1,
                const float* __restrict__ W2,
                const float* __restrict__ b2,
                const float* __restrict__ W3,
                const float* __restrict__ b3,
                const float* __restrict__ nohist,
                float* __restrict__ out)
{
    extern __shared__ __align__(16) float sm[];
    float* sMp  = sm + OFF_MP;
    float* sW2p = sm + OFF_W2P;
    float* sH1  = sm + OFF_H1;
    float* sQa  = sm + OFF_QA;
    float* sW3  = sm + OFF_W3;
    float* sB2  = sm + OFF_B2;
    float* sS   = sm + OFF_S;
    int*   sIdx = reinterpret_cast<int*>(sm + OFF_IDX);
    int*   sCnt = reinterpret_cast<int*>(sm + OFF_CNT);
    float* sRed = sm + OFF_RED;
    float* sPart= sm + OFF_PART;

    const int tid  = threadIdx.x;
    const int lane = tid & 31;
    const int warp = tid >> 5;
    const int b    = blockIdx.x;

    const float* qg = query + (size_t)b * E;

    // ---------- phase A: Mp, W2p, qa partials, mask ballot ----------
    // Mp[ep][2h+s] = m[2ep+s][h], m[e][h] = W1b - W1d + q[e]*W1c
    for (int i = tid; i < E * H; i += NT) {
        const int e = i >> 6, h = i & (H - 1);
        const float v = __ldg(W1 + (128 + e) * H + h) - __ldg(W1 + (384 + e) * H + h)
                      + __ldg(qg + e) * __ldg(W1 + (256 + e) * H + h);
        sMp[(e >> 1) * 128 + 2 * h + (e & 1)] = v;
    }
    for (int i = tid; i < H * H; i += NT) {
        const int hp = i >> 7, c = i & 127;
        sW2p[i] = __ldg(W2 + (2 * hp + (c & 1)) * H + (c >> 1));
    }
    {   // qa partials: 5 e-chunks x 64 h
        const int h = tid & (H - 1);
        const int r = tid >> 6;
        const int e0 = r * 26;
        const int e1 = (e0 + 26 < E) ? e0 + 26 : E;
        float acc = 0.f;
        for (int e = e0; e < e1; ++e)
            acc += __ldg(qg + e) * (__ldg(W1 + e * H + h) + __ldg(W1 + (384 + e) * H + h));
        sPart[r * H + h] = acc;
    }
    if (tid < H) { sW3[tid] = W3[tid]; sB2[tid] = b2[tid]; }

    // mask ballot (warps 0..6 cover 224 >= 200 slots)
    int mbit = 0, pre = 0;
    if (warp < 7) {
        mbit = (tid < L) ? (__ldg(mask + b * L + tid) != 0) : 0;
        const unsigned bal = __ballot_sync(0xffffffffu, mbit);
        pre = __popc(bal & ((1u << lane) - 1u));
        if (lane == 0) sCnt[warp] = __popc(bal);
    }
    __syncthreads();

    if (tid < H) {
        float acc = b1[tid];
        #pragma unroll
        for (int r = 0; r < 5; ++r) acc += sPart[r * H + tid];
        sQa[tid] = acc;
    }
    if (tid == 0) {
        int s = 0;
        #pragma unroll
        for (int w = 0; w < 7; ++w) { const int c = sCnt[w]; sCnt[w] = s; s += c; }
        sCnt[7] = s;
    }
    __syncthreads();
    if (warp < 7 && mbit) sIdx[sCnt[warp] + pre] = tid;
    __syncthreads();

    const int cnt = sCnt[7];
    const int nt  = (cnt + 9) / 10;          // 10-key tiles over compacted list

    // ---------- scorer over compacted keys ----------
    const char* kbase = reinterpret_cast<const char*>(keys + (size_t)b * (L * E));
    const ulonglong2* mrow  = reinterpret_cast<const ulonglong2*>(sMp  + 4 * lane);
    const ulonglong2* w2row = reinterpret_cast<const ulonglong2*>(sW2p + 4 * lane);
    float* h1w = sH1 + warp * 640;           // 32 rows x 20 f
    const float qax = sQa[2 * lane], qay = sQa[2 * lane + 1];
    const float w3x = sW3[2 * lane], w3y = sW3[2 * lane + 1];
    const float b2x = sB2[2 * lane], b2y = sB2[2 * lane + 1];
    const float b3v = b3[0];

    for (int tile = warp; tile < nt; tile += NW) {
        const int l0 = tile * 10;
        const char* kr[10];
        #pragma unroll
        for (int j = 0; j < 10; ++j) {
            const int l = l0 + j;
            kr[j] = kbase + (size_t)sIdx[(l < cnt) ? l : (cnt - 1)] * (E * 4);
        }

        // GEMM1: 10 keys x 64 h, K=128 (32 steps of 4 e), 2x5 key batches
        ull acc[10][2];
        #pragma unroll
        for (int j = 0; j < 10; ++j) { acc[j][0] = 0ull; acc[j][1] = 0ull; }

        for (int ep2 = 0; ep2 < 32; ++ep2) {
            const ulonglong2 mA = mrow[(2 * ep2) * 32];
            const ulonglong2 mB = mrow[(2 * ep2 + 1) * 32];
            {
                ulonglong2 kv[5];
                #pragma unroll
                for (int j = 0; j < 5; ++j) kv[j] = ldg128(kr[j] + ep2 * 16);
                #pragma unroll
                for (int j = 0; j < 5; ++j) {
                    ffma2(acc[j][0], kv[j].x, mA.x); ffma2(acc[j][1], kv[j].x, mA.y);
                    ffma2(acc[j][0], kv[j].y, mB.x); ffma2(acc[j][1], kv[j].y, mB.y);
                }
            }
            {
                ulonglong2 kv[5];
                #pragma unroll
                for (int j = 0; j < 5; ++j) kv[j] = ldg128(kr[5 + j] + ep2 * 16);
                #pragma unroll
                for (int j = 0; j < 5; ++j) {
                    ffma2(acc[5 + j][0], kv[j].x, mA.x); ffma2(acc[5 + j][1], kv[j].x, mA.y);
                    ffma2(acc[5 + j][0], kv[j].y, mB.x); ffma2(acc[5 + j][1], kv[j].y, mB.y);
                }
            }
        }

        // h1 write: lane owns row hp=lane; float4 = 2 keys x (2h of lane)
        {
            float* dst = h1w + lane * 20;
            #pragma unroll
            for (int jp = 0; jp < 5; ++jp) {
                const float2 a0 = upk(acc[2 * jp][0]);
                const float2 a1 = upk(acc[2 * jp][1]);
                const float2 c0 = upk(acc[2 * jp + 1][0]);
                const float2 c1 = upk(acc[2 * jp + 1][1]);
                float4 o;
                o.x = fmaxf(a0.x + a0.y + qax, 0.f);
                o.y = fmaxf(a1.x + a1.y + qay, 0.f);
                o.z = fmaxf(c0.x + c0.y + qax, 0.f);
                o.w = fmaxf(c1.x + c1.y + qay, 0.f);
                *reinterpret_cast<float4*>(dst + 4 * jp) = o;
            }
        }
        __syncwarp();

        // GEMM2: 10 keys x 64 h', K=64 (32 h-pair steps)
        ull acc2[10][2];
        #pragma unroll
        for (int j = 0; j < 10; ++j) { acc2[j][0] = 0ull; acc2[j][1] = 0ull; }

        for (int hp = 0; hp < 32; ++hp) {
            const ull* hrow = reinterpret_cast<const ull*>(h1w + hp * 20);
            const ulonglong2 hA = *reinterpret_cast<const ulonglong2*>(hrow);
            const ulonglong2 hB = *reinterpret_cast<const ulonglong2*>(hrow + 2);
            const ulonglong2 hC = *reinterpret_cast<const ulonglong2*>(hrow + 4);
            const ulonglong2 hD = *reinterpret_cast<const ulonglong2*>(hrow + 6);
            const ulonglong2 hE = *reinterpret_cast<const ulonglong2*>(hrow + 8);
            const ulonglong2 wv = w2row[hp * 32];
            ffma2(acc2[0][0], hA.x, wv.x); ffma2(acc2[0][1], hA.x, wv.y);
            ffma2(acc2[1][0], hA.y, wv.x); ffma2(acc2[1][1], hA.y, wv.y);
            ffma2(acc2[2][0], hB.x, wv.x); ffma2(acc2[2][1], hB.x, wv.y);
            ffma2(acc2[3][0], hB.y, wv.x); ffma2(acc2[3][1], hB.y, wv.y);
            ffma2(acc2[4][0], hC.x, wv.x); ffma2(acc2[4][1], hC.x, wv.y);
            ffma2(acc2[5][0], hC.y, wv.x); ffma2(acc2[5][1], hC.y, wv.y);
            ffma2(acc2[6][0], hD.x, wv.x); ffma2(acc2[6][1], hD.x, wv.y);
            ffma2(acc2[7][0], hD.y, wv.x); ffma2(acc2[7][1], hD.y, wv.y);
            ffma2(acc2[8][0], hE.x, wv.x); ffma2(acc2[8][1], hE.x, wv.y);
            ffma2(acc2[9][0], hE.y, wv.x); ffma2(acc2[9][1], hE.y, wv.y);
        }

        // layer 3 + butterfly; store only valid compacted slots
        #pragma unroll
        for (int jp = 0; jp < 5; ++jp) {
            const float2 e0 = upk(acc2[2 * jp][0]);
            const float2 e1 = upk(acc2[2 * jp][1]);
            const float2 f0 = upk(acc2[2 * jp + 1][0]);
            const float2 f1 = upk(acc2[2 * jp + 1][1]);
            float pa = fmaxf(e0.x + e0.y + b2x, 0.f) * w3x
                     + fmaxf(e1.x + e1.y + b2y, 0.f) * w3y;
            float pb = fmaxf(f0.x + f0.y + b2x, 0.f) * w3x
                     + fmaxf(f1.x + f1.y + b2y, 0.f) * w3y;
            #pragma unroll
            for (int o = 16; o > 0; o >>= 1) {
                pa += __shfl_xor_sync(0xffffffffu, pa, o);
                pb += __shfl_xor_sync(0xffffffffu, pb, o);
            }
            if (lane == 0) {
                if (l0 + 2 * jp < cnt)     sS[l0 + 2 * jp]     = pa + b3v;
                if (l0 + 2 * jp + 1 < cnt) sS[l0 + 2 * jp + 1] = pb + b3v;
            }
        }
        __syncwarp();
    }
    __syncthreads();

    // ---------- softmax over compacted [0, cnt) ----------
    float vmax = -3.0e38f;
    if (tid < cnt) vmax = sS[tid];
    #pragma unroll
    for (int o = 16; o > 0; o >>= 1)
        vmax = fmaxf(vmax, __shfl_xor_sync(0xffffffffu, vmax, o));
    if (lane == 0) sRed[warp] = vmax;
    __syncthreads();
    if (warp == 0) {
        float v = (lane < NW) ? sRed[lane] : -3.0e38f;
        #pragma unroll
        for (int o = 16; o > 0; o >>= 1)
            v = fmaxf(v, __shfl_xor_sync(0xffffffffu, v, o));
        if (lane == 0) sRed[0] = v;
    }
    __syncthreads();
    const float smax = sRed[0];

    float p = 0.f;
    if (tid < cnt) p = __expf(sS[tid] - smax);
    float sp = p;
    #pragma unroll
    for (int o = 16; o > 0; o >>= 1)
        sp += __shfl_xor_sync(0xffffffffu, sp, o);
    if (lane == 0) sRed[warp] = sp;
    __syncthreads();
    if (tid < cnt) sS[tid] = p;
    if (warp == 0) {
        float a = (lane < NW) ? sRed[lane] : 0.f;
        #pragma unroll
        for (int o = 16; o > 0; o >>= 1)
            a += __shfl_xor_sync(0xffffffffu, a, o);
        if (lane == 0) sRed[0] = a;
    }
    __syncthreads();
    const bool  allpad = (cnt == 0);
    const float inv    = allpad ? 0.f : (1.0f / sRed[0]);

    // ---------- weighted sum over compacted keys (gmem gather) ----------
    if (tid < 256) {
        const int e = tid & 127;
        const int r = tid >> 7;
        const int half = (cnt + 1) >> 1;
        const int lb = r ? half : 0;
        const int le = r ? cnt : half;
        const float* kg = keys + (size_t)b * (L * E) + e;
        float acc = 0.f;
        for (int l = lb; l < le; ++l)
            acc += sS[l] * __ldg(kg + sIdx[l] * E);
        sPart[r * E + e] = acc;
    }
    __syncthreads();
    if (tid < E) {
        float o = (sPart[tid] + sPart[E + tid]) * inv;
        if (allpad) o = nohist[tid];
        out[b * E + tid] = o;
    }
}

extern "C" void kernel_launch(void* const* d_in, const int* in_sizes, int n_in,
                              void* d_out, int out_size) {
    const float* query = (const float*)d_in[0];
    const float* keys  = (const float*)d_in[1];
    const int*   mask  = (const int*)  d_in[2];
    const float* W1    = (const float*)d_in[3];
    const float* b1    = (const float*)d_in[4];
    const float* W2    = (const float*)d_in[5];
    const float* b2    = (const float*)d_in[6];
    const float* W3    = (const float*)d_in[7];
    const float* b3    = (const float*)d_in[8];
    const float* nh    = (const float*)d_in[9];
    float* out = (float*)d_out;

    cudaFuncSetAttribute(din_kernel, cudaFuncAttributeMaxDynamicSharedMemorySize,
                         SMEM_FLOATS * (int)sizeof(float));
    din_kernel<<<Bn, NT, SMEM_FLOATS * sizeof(float)>>>(
        query, keys, mask, W1, b1, W2, b2, W3, b3, nh, out);
}

// round 17
// speedup vs baseline: 1.6037x; 1.2639x over previous
#include <cuda_runtime.h>
#include <cstdint>

// DIN attention, B=2048, L=200, E=128, H=64, fp32.
// attn_in@W1 = qa_b + k @ M_b (per-batch M).
// Mask compaction: only ~50% unmasked keys are scored (exact vs reference:
// masked scores underflow to 0 anyway).
// Occupancy round: 4-key mini-tiles -> <=63 regs -> 2 CTAs x 512 thr
// = 32 warps/SM (8/SMSP) to cover LDG/LDS latency. Smem ~70KB/CTA.

namespace {
constexpr int Bn = 2048;
constexpr int L  = 200;
constexpr int E  = 128;
constexpr int H  = 64;
constexpr int NT = 512;   // 16 warps
constexpr int NW = 16;

// float offsets in dynamic smem
constexpr int OFF_MP  = 0;       // 64 ep x 128 = 8192 f
constexpr int OFF_W2P = 8192;    // 32 hp x 128 = 4096 f
constexpr int OFF_H1  = 12288;   // 16 warps x 32 rows x 8 f = 4096 f
constexpr int OFF_QA  = 16384;   // 64
constexpr int OFF_W3  = 16448;   // 64
constexpr int OFF_B2  = 16512;   // 64
constexpr int OFF_S   = 16576;   // 208 (compacted scores/probs)
constexpr int OFF_IDX = 16784;   // 200 ints
constexpr int OFF_CNT = 16984;   // 8 ints
constexpr int OFF_RED = 16992;   // 32
constexpr int OFF_PART= 17024;   // 512
constexpr int SMEM_FLOATS = 17536;   // 70144 bytes
}

typedef unsigned long long ull;

__device__ __forceinline__ void ffma2(ull& d, ull a, ull b) {
    asm("fma.rn.f32x2 %0, %1, %2, %0;" : "+l"(d) : "l"(a), "l"(b));
}
__device__ __forceinline__ float2 upk(ull v) {
    float2 r;
    asm("mov.b64 {%0, %1}, %2;" : "=f"(r.x), "=f"(r.y) : "l"(v));
    return r;
}
__device__ __forceinline__ ulonglong2 ldg128(const void* p) {
    ulonglong2 r;
    asm("ld.global.nc.v2.u64 {%0, %1}, [%2];" : "=l"(r.x), "=l"(r.y) : "l"(p));
    return r;
}

__global__ __launch_bounds__(NT, 2)
void din_kernel(const float* __restrict__ query,
                const float* __restrict__ keys,
                const int*   __restrict__ mask,
                const float* __restrict__ W1,
                const float* __restrict__ b1,
                const float* __restrict__ W2,
                const float* __restrict__ b2,
                const float* __restrict__ W3,
                const float* __restrict__ b3,
                const float* __restrict__ nohist,
                float* __restrict__ out)
{
    extern __shared__ __align__(16) float sm[];
    float* sMp  = sm + OFF_MP;
    float* sW2p = sm + OFF_W2P;
    float* sH1  = sm + OFF_H1;
    float* sQa  = sm + OFF_QA;
    float* sW3  = sm + OFF_W3;
    float* sB2  = sm + OFF_B2;
    float* sS   = sm + OFF_S;
    int*   sIdx = reinterpret_cast<int*>(sm + OFF_IDX);
    int*   sCnt = reinterpret_cast<int*>(sm + OFF_CNT);
    float* sRed = sm + OFF_RED;
    float* sPart= sm + OFF_PART;

    const int tid  = threadIdx.x;
    const int lane = tid & 31;
    const int warp = tid >> 5;
    const int b    = blockIdx.x;

    const float* qg = query + (size_t)b * E;

    // ---------- phase A: Mp, W2p, qa partials, mask ballot ----------
    for (int i = tid; i < E * H; i += NT) {
        const int e = i >> 6, h = i & (H - 1);
        const float v = __ldg(W1 + (128 + e) * H + h) - __ldg(W1 + (384 + e) * H + h)
                      + __ldg(qg + e) * __ldg(W1 + (256 + e) * H + h);
        sMp[(e >> 1) * 128 + 2 * h + (e & 1)] = v;
    }
    for (int i = tid; i < H * H; i += NT) {
        const int hp = i >> 7, c = i & 127;
        sW2p[i] = __ldg(W2 + (2 * hp + (c & 1)) * H + (c >> 1));
    }
    {   // qa partials: 8 e-chunks of 16 x 64 h
        const int h = tid & (H - 1);
        const int r = tid >> 6;              // 0..7
        const int e0 = r * 16;
        float acc = 0.f;
        #pragma unroll
        for (int e = e0; e < e0 + 16; ++e)
            acc += __ldg(qg + e) * (__ldg(W1 + e * H + h) + __ldg(W1 + (384 + e) * H + h));
        sPart[r * H + h] = acc;
    }
    if (tid < H) { sW3[tid] = W3[tid]; sB2[tid] = b2[tid]; }

    // mask ballot (warps 0..6 cover 224 >= 200 slots)
    int mbit = 0, pre = 0;
    if (warp < 7) {
        mbit = (tid < L) ? (__ldg(mask + b * L + tid) != 0) : 0;
        const unsigned bal = __ballot_sync(0xffffffffu, mbit);
        pre = __popc(bal & ((1u << lane) - 1u));
        if (lane == 0) sCnt[warp] = __popc(bal);
    }
    __syncthreads();

    if (tid < H) {
        float acc = b1[tid];
        #pragma unroll
        for (int r = 0; r < 8; ++r) acc += sPart[r * H + tid];
        sQa[tid] = acc;
    }
    if (tid == 0) {
        int s = 0;
        #pragma unroll
        for (int w = 0; w < 7; ++w) { const int c = sCnt[w]; sCnt[w] = s; s += c; }
        sCnt[7] = s;
    }
    __syncthreads();
    if (warp < 7 && mbit) sIdx[sCnt[warp] + pre] = tid;
    __syncthreads();

    const int cnt = sCnt[7];
    const int nt  = (cnt + 3) >> 2;          // 4-key mini-tiles

    // ---------- scorer over compacted keys ----------
    const char* kbase = reinterpret_cast<const char*>(keys + (size_t)b * (L * E));
    const ulonglong2* mrow  = reinterpret_cast<const ulonglong2*>(sMp  + 4 * lane);
    const ulonglong2* w2row = reinterpret_cast<const ulonglong2*>(sW2p + 4 * lane);
    float* h1w = sH1 + warp * 256;           // 32 rows x 8 f
    const float qax = sQa[2 * lane], qay = sQa[2 * lane + 1];
    const float w3x = sW3[2 * lane], w3y = sW3[2 * lane + 1];
    const float b2x = sB2[2 * lane], b2y = sB2[2 * lane + 1];
    const float b3v = b3[0];

    for (int tile = warp; tile < nt; tile += NW) {
        const int l0 = tile * 4;
        const char* kr0 = kbase + (size_t)sIdx[l0] * (E * 4);
        const char* kr1 = kbase + (size_t)sIdx[(l0 + 1 < cnt) ? l0 + 1 : cnt - 1] * (E * 4);
        const char* kr2 = kbase + (size_t)sIdx[(l0 + 2 < cnt) ? l0 + 2 : cnt - 1] * (E * 4);
        const char* kr3 = kbase + (size_t)sIdx[(l0 + 3 < cnt) ? l0 + 3 : cnt - 1] * (E * 4);

        // GEMM1: 4 keys x 64 h, K=128 (32 steps of 4 e)
        ull acc[4][2];
        #pragma unroll
        for (int j = 0; j < 4; ++j) { acc[j][0] = 0ull; acc[j][1] = 0ull; }

        for (int ep2 = 0; ep2 < 32; ++ep2) {
            const ulonglong2 k0 = ldg128(kr0 + ep2 * 16);
            const ulonglong2 k1 = ldg128(kr1 + ep2 * 16);
            const ulonglong2 k2 = ldg128(kr2 + ep2 * 16);
            const ulonglong2 k3 = ldg128(kr3 + ep2 * 16);
            const ulonglong2 mA = mrow[(2 * ep2) * 32];
            const ulonglong2 mB = mrow[(2 * ep2 + 1) * 32];
            ffma2(acc[0][0], k0.x, mA.x); ffma2(acc[0][1], k0.x, mA.y);
            ffma2(acc[0][0], k0.y, mB.x); ffma2(acc[0][1], k0.y, mB.y);
            ffma2(acc[1][0], k1.x, mA.x); ffma2(acc[1][1], k1.x, mA.y);
            ffma2(acc[1][0], k1.y, mB.x); ffma2(acc[1][1], k1.y, mB.y);
            ffma2(acc[2][0], k2.x, mA.x); ffma2(acc[2][1], k2.x, mA.y);
            ffma2(acc[2][0], k2.y, mB.x); ffma2(acc[2][1], k2.y, mB.y);
            ffma2(acc[3][0], k3.x, mA.x); ffma2(acc[3][1], k3.x, mA.y);
            ffma2(acc[3][0], k3.y, mB.x); ffma2(acc[3][1], k3.y, mB.y);
        }

        // h1 write: lane owns row hp=lane; 4 keys x (2h of lane) = 2 float4
        {
            float* dst = h1w + lane * 8;
            float4 o0, o1;
            const float2 a0 = upk(acc[0][0]), a1 = upk(acc[0][1]);
            const float2 c0 = upk(acc[1][0]), c1 = upk(acc[1][1]);
            o0.x = fmaxf(a0.x + a0.y + qax, 0.f);
            o0.y = fmaxf(a1.x + a1.y + qay, 0.f);
            o0.z = fmaxf(c0.x + c0.y + qax, 0.f);
            o0.w = fmaxf(c1.x + c1.y + qay, 0.f);
            const float2 d0 = upk(acc[2][0]), d1 = upk(acc[2][1]);
            const float2 g0 = upk(acc[3][0]), g1 = upk(acc[3][1]);
            o1.x = fmaxf(d0.x + d0.y + qax, 0.f);
            o1.y = fmaxf(d1.x + d1.y + qay, 0.f);
            o1.z = fmaxf(g0.x + g0.y + qax, 0.f);
            o1.w = fmaxf(g1.x + g1.y + qay, 0.f);
            *reinterpret_cast<float4*>(dst)     = o0;
            *reinterpret_cast<float4*>(dst + 4) = o1;
        }
        __syncwarp();

        // GEMM2: 4 keys x 64 h', K=64 (32 h-pair steps)
        ull acc2[4][2];
        #pragma unroll
        for (int j = 0; j < 4; ++j) { acc2[j][0] = 0ull; acc2[j][1] = 0ull; }

        for (int hp = 0; hp < 32; ++hp) {
            const ull* hrow = reinterpret_cast<const ull*>(h1w + hp * 8);
            const ulonglong2 hA = *reinterpret_cast<const ulonglong2*>(hrow);
            const ulonglong2 hB = *reinterpret_cast<const ulonglong2*>(hrow + 2);
            const ulonglong2 wv = w2row[hp * 32];
            ffma2(acc2[0][0], hA.x, wv.x); ffma2(acc2[0][1], hA.x, wv.y);
            ffma2(acc2[1][0], hA.y, wv.x); ffma2(acc2[1][1], hA.y, wv.y);
            ffma2(acc2[2][0], hB.x, wv.x); ffma2(acc2[2][1], hB.x, wv.y);
            ffma2(acc2[3][0], hB.y, wv.x); ffma2(acc2[3][1], hB.y, wv.y);
        }

        // layer 3 + butterfly; store only valid compacted slots
        #pragma unroll
        for (int j = 0; j < 4; ++j) {
            const float2 e0 = upk(acc2[j][0]);
            const float2 e1 = upk(acc2[j][1]);
            float p = fmaxf(e0.x + e0.y + b2x, 0.f) * w3x
                    + fmaxf(e1.x + e1.y + b2y, 0.f) * w3y;
            #pragma unroll
            for (int o = 16; o > 0; o >>= 1)
                p += __shfl_xor_sync(0xffffffffu, p, o);
            if (lane == 0 && l0 + j < cnt) sS[l0 + j] = p + b3v;
        }
        __syncwarp();
    }
    __syncthreads();

    // ---------- softmax over compacted [0, cnt) ----------
    float vmax = -3.0e38f;
    if (tid < cnt) vmax = sS[tid];
    #pragma unroll
    for (int o = 16; o > 0; o >>= 1)
        vmax = fmaxf(vmax, __shfl_xor_sync(0xffffffffu, vmax, o));
    if (lane == 0) sRed[warp] = vmax;
    __syncthreads();
    if (warp == 0) {
        float v = (lane < NW) ? sRed[lane] : -3.0e38f;
        #pragma unroll
        for (int o = 16; o > 0; o >>= 1)
            v = fmaxf(v, __shfl_xor_sync(0xffffffffu, v, o));
        if (lane == 0) sRed[0] = v;
    }
    __syncthreads();
    const float smax = sRed[0];

    float p = 0.f;
    if (tid < cnt) p = __expf(sS[tid] - smax);
    float sp = p;
    #pragma unroll
    for (int o = 16; o > 0; o >>= 1)
        sp += __shfl_xor_sync(0xffffffffu, sp, o);
    if (lane == 0) sRed[warp] = sp;
    __syncthreads();
    if (tid < cnt) sS[tid] = p;
    if (warp == 0) {
        float a = (lane < NW) ? sRed[lane] : 0.f;
        #pragma unroll
        for (int o = 16; o > 0; o >>= 1)
            a += __shfl_xor_sync(0xffffffffu, a, o);
        if (lane == 0) sRed[0] = a;
    }
    __syncthreads();
    const bool  allpad = (cnt == 0);
    const float inv    = allpad ? 0.f : (1.0f / sRed[0]);

    // ---------- weighted sum over compacted keys (gmem gather) ----------
    {
        const int e = tid & 127;
        const int r = tid >> 7;              // 0..3 quarters
        const int lb = (r * cnt) >> 2;
        const int le = ((r + 1) * cnt) >> 2;
        const float* kg = keys + (size_t)b * (L * E) + e;
        float acc = 0.f;
        for (int l = lb; l < le; ++l)
            acc += sS[l] * __ldg(kg + sIdx[l] * E);
        sPart[r * E + e] = acc;
    }
    __syncthreads();
    if (tid < E) {
        float o = (sPart[tid] + sPart[E + tid] + sPart[2 * E + tid] + sPart[3 * E + tid]) * inv;
        if (allpad) o = nohist[tid];
        out[b * E + tid] = o;
    }
}

extern "C" void kernel_launch(void* const* d_in, const int* in_sizes, int n_in,
                              void* d_out, int out_size) {
    const float* query = (const float*)d_in[0];
    const float* keys  = (const float*)d_in[1];
    const int*   mask  = (const int*)  d_in[2];
    const float* W1    = (const float*)d_in[3];
    const float* b1    = (const float*)d_in[4];
    const float* W2    = (const float*)d_in[5];
    const float* b2    = (const float*)d_in[6];
    const float* W3    = (const float*)d_in[7];
    const float* b3    = (const float*)d_in[8];
    const float* nh    = (const float*)d_in[9];
    float* out = (float*)d_out;

    cudaFuncSetAttribute(din_kernel, cudaFuncAttributeMaxDynamicSharedMemorySize,
                         SMEM_FLOATS * (int)sizeof(float));
    din_kernel<<<Bn, NT, SMEM_FLOATS * sizeof(float)>>>(
        query, keys, mask, W1, b1, W2, b2, W3, b3, nh, out);
}